// round 11
// baseline (speedup 1.0000x reference)
#include <cuda_runtime.h>
#include <cstdint>

// ------------------------------ helpers ------------------------------------
__device__ __forceinline__ uint32_t f32_tf32(float f) {
    uint32_t u;
    asm("cvt.rna.tf32.f32 %0, %1;" : "=r"(u) : "f"(f));
    return u;
}
__device__ __forceinline__ uint32_t smem_u32(const void* p) {
    uint32_t a;
    asm("{ .reg .u64 t; cvta.to.shared.u64 t, %1; cvt.u32.u64 %0, t; }"
        : "=r"(a) : "l"(p));
    return a;
}
__device__ __forceinline__ void cp_async16(uint32_t saddr, const void* gaddr,
                                           uint32_t src_sz) {
    asm volatile("cp.async.cg.shared.global [%0], [%1], 16, %2;"
                 :: "r"(saddr), "l"(gaddr), "r"(src_sz) : "memory");
}
#define CP_COMMIT() asm volatile("cp.async.commit_group;" ::: "memory")
#define CP_WAIT(n)  asm volatile("cp.async.wait_group %0;" :: "n"(n) : "memory")

// D += A*B, m16n8k8 tf32 (tensor pipe, fp32 accumulate in registers)
__device__ __forceinline__ void mma_tf32(float* d, const uint32_t* a,
                                         const uint32_t* b) {
    asm volatile(
        "mma.sync.aligned.m16n8k8.row.col.f32.tf32.tf32.f32 "
        "{%0,%1,%2,%3}, {%4,%5,%6,%7}, {%8,%9}, {%0,%1,%2,%3};"
        : "+f"(d[0]), "+f"(d[1]), "+f"(d[2]), "+f"(d[3])
        : "r"(a[0]), "r"(a[1]), "r"(a[2]), "r"(a[3]), "r"(b[0]), "r"(b[1]));
}

// ---------------------------------------------------------------------------
// Single fused kernel: kernel-MLP (prologue, hidden under cp.async loads) +
// dynamic depthwise 3x3 + LeakyReLU -> tf32 mma.sync GEMM (1x1) + bias.
// da_conv body is byte-identical to the R9-verified version.
//
// Grid (4,16,16): block = 32x8 pixel tile of one batch, 256 threads (8 warps).
// GEMM: M=256 pixels, N=64 outputs, K=64 channels, 4 chunks of 16.
//
// Smem (bytes):
//   xs[2] @0     : halo chunk, 16ch x 10r x 44f (176B rows), 2 bufs  (56320)
//                  (reused as 32x264 epilogue stage after GEMM)
//   vs    @56320 : V tf32, 16 x 296 floats                           (18944)
//   wct   @75264 : Wc tf32, [k=c][n=o] stride 72                     (18432)
//   kk    @93696 : 64 x 12 f32 (per-batch 3x3 kernels, MLP output)   ( 3072)
//   bcs   @96768 : bias f32[64]                                      (  256)
//   ds    @97024 : d[b] f32[64]                                      (  256)
//   hid   @97280 : MLP hidden f32[64]                                (  256)
// total 97536 -> 2 blocks/SM.
// ---------------------------------------------------------------------------
#define KC          16
#define XS_OFF      0
#define XS_BUF      28160            // 16*440*4
#define VS_OFF      56320
#define WCT_OFF     75264
#define KK_OFF      93696
#define BC_OFF      96768
#define DS_OFF      97024
#define HID_OFF     97280
#define SMEM_TOTAL  97536
#define KS          296
#define WCT_STRIDE  72
#define STG_STRIDE  264

__global__ __launch_bounds__(256, 2)
void da_conv_mma(const float* __restrict__ x,
                 const float* __restrict__ dvec,
                 const float* __restrict__ Wk1,
                 const float* __restrict__ Wk2,
                 const float* __restrict__ Wc,
                 const float* __restrict__ bc,
                 float* __restrict__ out) {
    extern __shared__ char smem[];
    const uint32_t smb = smem_u32(smem);
    uint32_t* wct = (uint32_t*)(smem + WCT_OFF);
    float*    kk  = (float*)(smem + KK_OFF);
    float*    bcs = (float*)(smem + BC_OFF);
    float*    ds  = (float*)(smem + DS_OFF);
    float*    hid = (float*)(smem + HID_OFF);

    const int t  = threadIdx.x;
    const int b  = blockIdx.z, bx = blockIdx.x, by = blockIdx.y;
    const int w  = t >> 5, lane = t & 31;

    // ---- halo loader: 16B cp.async, slab mapping (threads 0..159) ---------
    const int h0  = by * 8 - 1;
    const int w0p = bx * 32;
    const float* xb = x + (size_t)b * 64 * 16384;

    const int  lcl = t & 15;            // channel-in-chunk this thread loads
    const int  lk  = t >> 4;            // 16B chunk index 0..9 (t<160)
    const int  cb  = w0p - 4 + lk * 4;  // global col of chunk start
    const bool vc  = (unsigned)cb <= 124u;
    const bool lactive = t < 160;
    const float* lsrc0 = xb + (size_t)lcl * 16384 + (vc ? cb : 0);
    const uint32_t ldst0 = smb + XS_OFF + (uint32_t)(lcl * 1760 + lk * 16);

    auto load_chunk = [&](int c, int buf) {
        if (lactive) {
            const float* s0 = lsrc0 + (size_t)c * KC * 16384;
            uint32_t d0 = ldst0 + (uint32_t)buf * XS_BUF;
#pragma unroll
            for (int r = 0; r < 10; r++) {
                int gh = h0 + r;
                bool v = vc && ((unsigned)gh < 128u);
                cp_async16(d0 + r * 176, s0 + (v ? gh * 128 : 0), v ? 16u : 0u);
            }
        }
        CP_COMMIT();
    };

    // issue the first two chunk loads BEFORE the MLP — MLP hides under them
    load_chunk(0, 0);
    load_chunk(1, 1);

    // ---- static tiles: Wc -> wct (tf32), bias, d --------------------------
    for (int i = t; i < 4096; i += 256) {
        int o = i >> 6, c = i & 63;
        wct[c * WCT_STRIDE + o] = f32_tf32(Wc[i]);
    }
    if (t < 64) bcs[t] = bc[t];
    if (t < 64) ds[t] = dvec[b * 64 + t];
    __syncthreads();

    // ---- kernel-MLP layer 1: hid = lrelu(d @ Wk1^T); warp-per-output ------
    {
        const float d0 = ds[lane];
        const float d1 = ds[lane + 32];
#pragma unroll
        for (int q = 0; q < 8; q++) {
            const int m = w * 8 + q;
            const float* wp = Wk1 + (size_t)m * 64;
            float p = d0 * wp[lane] + d1 * wp[lane + 32];
#pragma unroll
            for (int sh = 16; sh > 0; sh >>= 1)
                p += __shfl_xor_sync(0xFFFFFFFFu, p, sh);
            if (lane == 0) hid[m] = (p >= 0.f) ? p : 0.1f * p;
        }
    }
    __syncthreads();

    // ---- kernel-MLP layer 2: kern = hid @ Wk2^T -> kk (stride 12) ---------
    {
        const float h0v = hid[lane];
        const float h1v = hid[lane + 32];
#pragma unroll 8
        for (int q = 0; q < 72; q++) {
            const int m = w * 72 + q;            // 0..575
            const float* wp = Wk2 + (size_t)m * 64;
            float p = h0v * wp[lane] + h1v * wp[lane + 32];
#pragma unroll
            for (int sh = 16; sh > 0; sh >>= 1)
                p += __shfl_xor_sync(0xFFFFFFFFu, p, sh);
            if (lane == 0) {
                int c = m / 9, j = m - c * 9;
                kk[c * 12 + j] = p;
            }
        }
    }
    // kk visibility for phase 1 is covered by the first loop-iteration sync.

    // ---- GEMM thread mapping (fragment layout verified R5-R9) -------------
    const int wm = w >> 1, wn = w & 1;
    const int g = lane >> 2, tig = lane & 3;
    const int m_base = wm * 64;
    const int n_base = wn * 32;

    // per-mt vs offsets: R = wm*2 + (mt>>1), C = (mt&1)*16 + g
    int rowoff[4];
#pragma unroll
    for (int mt = 0; mt < 4; mt++)
        rowoff[mt] = (wm * 2 + (mt >> 1)) * 36 + (mt & 1) * 16 + g;

    float acc[4][4][4];
#pragma unroll
    for (int mt = 0; mt < 4; mt++)
#pragma unroll
        for (int nt = 0; nt < 4; nt++)
#pragma unroll
            for (int r = 0; r < 4; r++) acc[mt][nt][r] = 0.f;

    // ---- phase-1 mapping: 16 px x 1 row x 1 ch per thread -----------------
    const int ch_l = t >> 4;            // channel in chunk 0..15
    const int prw  = (t >> 1) & 7;      // output row 0..7
    const int psh  = t & 1;             // col half 0..1

    uint32_t* vs = (uint32_t*)(smem + VS_OFF);

#pragma unroll
    for (int c = 0; c < 4; c++) {
        const int buf = c & 1;
        if (c < 3) { CP_WAIT(1); } else { CP_WAIT(0); }
        __syncthreads();

        // ---- phase 1: dwconv 3x3 + lrelu, 16px x 1ch per thread -----------
        {
            const float* xs = (const float*)(smem + XS_OFF + buf * XS_BUF);
            const float* kcp = kk + (c * KC + ch_l) * 12;
            const float* xbase = xs + ch_l * 440 + prw * 44 + 16 * psh;

            float a16[16];
#pragma unroll
            for (int p = 0; p < 16; p++) a16[p] = 0.f;

#pragma unroll
            for (int r = 0; r < 3; r++) {
                float k0 = kcp[r * 3 + 0];
                float k1 = kcp[r * 3 + 1];
                float k2 = kcp[r * 3 + 2];
                const float4* xr = (const float4*)(xbase + r * 44);
                float4 f0 = xr[0], f1 = xr[1], f2 = xr[2];
                float4 f3 = xr[3], f4 = xr[4], f5 = xr[5];
                float v[24] = {f0.x, f0.y, f0.z, f0.w, f1.x, f1.y, f1.z, f1.w,
                               f2.x, f2.y, f2.z, f2.w, f3.x, f3.y, f3.z, f3.w,
                               f4.x, f4.y, f4.z, f4.w, f5.x, f5.y, f5.z, f5.w};
#pragma unroll
                for (int p = 0; p < 16; p++)
                    a16[p] += v[p + 3] * k0 + v[p + 4] * k1 + v[p + 5] * k2;
            }

            uint32_t* vrow = vs + ch_l * KS + prw * 36 + 16 * psh;
#pragma unroll
            for (int q = 0; q < 4; q++) {
                float v0 = fmaxf(a16[4 * q + 0], 0.1f * a16[4 * q + 0]);
                float v1 = fmaxf(a16[4 * q + 1], 0.1f * a16[4 * q + 1]);
                float v2 = fmaxf(a16[4 * q + 2], 0.1f * a16[4 * q + 2]);
                float v3 = fmaxf(a16[4 * q + 3], 0.1f * a16[4 * q + 3]);
                *(uint4*)(vrow + 4 * q) = make_uint4(
                    f32_tf32(v0), f32_tf32(v1), f32_tf32(v2), f32_tf32(v3));
            }
        }
        __syncthreads();

        // prefetch chunk c+2 into the buffer we just drained
        if (c < 2) load_chunk(c + 2, buf);

        // ---- phase 2: 2 k-steps of the tf32 tensor GEMM -------------------
#pragma unroll
        for (int s2 = 0; s2 < 2; s2++) {
            const int k0 = s2 * 8;
            uint32_t bf[4][2];
#pragma unroll
            for (int nt = 0; nt < 4; nt++) {
                int n = n_base + nt * 8 + g;
                bf[nt][0] = wct[(c * KC + k0 + tig) * WCT_STRIDE + n];
                bf[nt][1] = wct[(c * KC + k0 + tig + 4) * WCT_STRIDE + n];
            }
            uint32_t af[4][4];
#pragma unroll
            for (int mt = 0; mt < 4; mt++) {
                af[mt][0] = vs[(k0 + tig) * KS + rowoff[mt]];
                af[mt][1] = vs[(k0 + tig) * KS + rowoff[mt] + 8];
                af[mt][2] = vs[(k0 + tig + 4) * KS + rowoff[mt]];
                af[mt][3] = vs[(k0 + tig + 4) * KS + rowoff[mt] + 8];
            }
#pragma unroll
            for (int mt = 0; mt < 4; mt++)
#pragma unroll
                for (int nt = 0; nt < 4; nt++)
                    mma_tf32(acc[mt][nt], af[mt], bf[nt]);
        }
    }

    // ---- epilogue: stage through smem (xs region, now free) -> STG --------
    float* stage = (float*)(smem + XS_OFF);
    float* obase = out + (size_t)b * 64 * 16384 + (size_t)(by * 8) * 128 + bx * 32;
    __syncthreads();
#pragma unroll
    for (int nc = 0; nc < 2; nc++) {
        if (wn == nc) {
#pragma unroll
            for (int mt = 0; mt < 4; mt++)
#pragma unroll
                for (int nt = 0; nt < 4; nt++) {
                    int ol = nt * 8 + 2 * tig;
                    int p0 = m_base + mt * 16 + g;
                    stage[ol * STG_STRIDE + p0]            = acc[mt][nt][0];
                    stage[(ol + 1) * STG_STRIDE + p0]      = acc[mt][nt][1];
                    stage[ol * STG_STRIDE + p0 + 8]        = acc[mt][nt][2];
                    stage[(ol + 1) * STG_STRIDE + p0 + 8]  = acc[mt][nt][3];
                }
        }
        __syncthreads();
#pragma unroll 8
        for (int j = 0; j < 32; j++) {
            int idx = t + 256 * j;
            int ol = idx >> 8, pix = idx & 255;
            float v = stage[ol * STG_STRIDE + pix] + bcs[nc * 32 + ol];
            obase[(size_t)(nc * 32 + ol) * 16384 + (pix >> 5) * 128 + (pix & 31)] = v;
        }
        __syncthreads();
    }
}

// ---------------------------------------------------------------------------
// Launch: inputs x, d, Wk1, Wk2, Wc, bc. Output float32 (16,64,128,128).
// Single fused kernel.
// ---------------------------------------------------------------------------
extern "C" void kernel_launch(void* const* d_in, const int* in_sizes, int n_in,
                              void* d_out, int out_size) {
    const float* x   = (const float*)d_in[0];
    const float* d   = (const float*)d_in[1];
    const float* Wk1 = (const float*)d_in[2];
    const float* Wk2 = (const float*)d_in[3];
    const float* Wc  = (const float*)d_in[4];
    const float* bc  = (const float*)d_in[5];
    float* out = (float*)d_out;

    cudaFuncSetAttribute(da_conv_mma,
                         cudaFuncAttributeMaxDynamicSharedMemorySize,
                         SMEM_TOTAL);
    dim3 grid(4, 16, 16);
    da_conv_mma<<<grid, 256, SMEM_TOTAL>>>(x, d, Wk1, Wk2, Wc, bc, out);
}

// round 15
// speedup vs baseline: 1.3904x; 1.3904x over previous
#include <cuda_runtime.h>
#include <cuda_fp16.h>
#include <cstdint>

// Scratch for per-(batch,channel) generated 3x3 kernels: 16*64*9 floats.
__device__ float g_kern[16 * 576];

// ------------------------------ helpers ------------------------------------
__device__ __forceinline__ uint32_t smem_u32(const void* p) {
    uint32_t a;
    asm("{ .reg .u64 t; cvta.to.shared.u64 t, %1; cvt.u32.u64 %0, t; }"
        : "=r"(a) : "l"(p));
    return a;
}
__device__ __forceinline__ void cp_async16(uint32_t saddr, const void* gaddr,
                                           uint32_t src_sz) {
    asm volatile("cp.async.cg.shared.global [%0], [%1], 16, %2;"
                 :: "r"(saddr), "l"(gaddr), "r"(src_sz) : "memory");
}
#define CP_COMMIT() asm volatile("cp.async.commit_group;" ::: "memory")
#define CP_WAIT(n)  asm volatile("cp.async.wait_group %0;" :: "n"(n) : "memory")

// D += A*B, m16n8k16 f16 inputs, fp32 accumulate (tensor pipe)
__device__ __forceinline__ void mma_f16(float* d, const uint32_t* a,
                                        const uint32_t* b) {
    asm volatile(
        "mma.sync.aligned.m16n8k16.row.col.f32.f16.f16.f32 "
        "{%0,%1,%2,%3}, {%4,%5,%6,%7}, {%8,%9}, {%0,%1,%2,%3};"
        : "+f"(d[0]), "+f"(d[1]), "+f"(d[2]), "+f"(d[3])
        : "r"(a[0]), "r"(a[1]), "r"(a[2]), "r"(a[3]), "r"(b[0]), "r"(b[1]));
}

__device__ __forceinline__ uint32_t pack_h2(float lo, float hi) {
    __half2 h = __halves2half2(__float2half_rn(lo), __float2half_rn(hi));
    return *reinterpret_cast<uint32_t*>(&h);
}

// ---------------------------------------------------------------------------
// Kernel A: kernel-generating MLP. (R9-verified, unchanged)
// Grid (16,9) x 256 threads; layer 2 warp-per-output, coalesced + shfl.
// ---------------------------------------------------------------------------
__global__ void gen_kern_kernel(const float* __restrict__ d,
                                const float* __restrict__ Wk1,
                                const float* __restrict__ Wk2) {
    const int b = blockIdx.x;
    const int t = threadIdx.x;  // 0..255
    const int w = t >> 5, lane = t & 31;
    __shared__ float ds[64];
    __shared__ float hid[64];

    if (t < 64) ds[t] = d[b * 64 + t];
    __syncthreads();
    if (t < 64) {
        float s = 0.f;
#pragma unroll 16
        for (int i = 0; i < 64; i++) s += ds[i] * Wk1[t * 64 + i];
        hid[t] = (s >= 0.f) ? s : 0.1f * s;
    }
    __syncthreads();

    const float h0 = hid[lane];
    const float h1 = hid[lane + 32];
#pragma unroll
    for (int q = 0; q < 8; q++) {
        const int m = blockIdx.y * 64 + w * 8 + q;
        const float* wp = Wk2 + (size_t)m * 64;
        float p = h0 * wp[lane] + h1 * wp[lane + 32];
#pragma unroll
        for (int sh = 16; sh > 0; sh >>= 1)
            p += __shfl_xor_sync(0xFFFFFFFFu, p, sh);
        if (lane == 0) g_kern[b * 576 + m] = p;
    }
}

// ---------------------------------------------------------------------------
// Kernel B: fused dynamic depthwise 3x3 + LeakyReLU -> f16 mma.sync GEMM
// (pointwise 1x1, m16n8k16, fp32 accum) + bias; cp.async channel pipeline.
//
// Grid (4,16,16): block = 32x8 pixel tile of one batch, 256 threads (8 warps).
// GEMM: M=256 pixels, N=64 outputs, K=64 channels, 4 chunks of 16; each
// chunk = ONE m16n8k16 k-step (channel pairs packed in half2).
//
// Phase-1 compute identical to R9 (16px x 1ch per thread, 18 LDS.128/16px,
// conflict-free). Channel pairing: thread t partners t^16 (same pixels,
// adjacent channel) via shfl_xor(16) + byte_perm; even-channel lanes store.
//
// vs16 layout: [ch-pair j=0..7][pixel], row stride KS16=296 uint32
// (296%32==8): pixel px at (px>>5)*36 + (px&31), max 283 < 296.
// af banks (8*tig+g) distinct; writer STS.128 banks distinct per phase.
// wct16: [global ch-pair j=0..31][n], stride 72, half2(Wc[n][2j],Wc[n][2j+1]).
//
// Smem (bytes), total 78336 -> 2 blocks/SM:
//   xs[2]  @0     : halo chunk, 16ch x 10r x 44f (176B rows), 2 bufs (56320)
//   vs16   @56320 : V f16 pairs, 8 x 296 uint32                      (9472)
//   wct16  @65792 : Wc f16 pairs, 32 x 72 uint32                     (9216)
//   kk     @75008 : 64 x 12 f32                                      (3072)
//   bcs    @78080 : bias f32[64]                                     ( 256)
// Epilogue stage (64 x 264 f32 = 67584 B) overlays xs+vs16 (dead).
// ---------------------------------------------------------------------------
#define KC          16
#define XS_OFF      0
#define XS_BUF      28160            // 16*440*4
#define VS_OFF      56320
#define WCT_OFF     65792
#define KK_OFF      75008
#define BC_OFF      78080
#define SMEM_TOTAL  78336
#define KS16        296
#define WCT_STRIDE  72
#define STG_STRIDE  264

__global__ __launch_bounds__(256, 2)
void da_conv_mma(const float* __restrict__ x,
                 const float* __restrict__ Wc,
                 const float* __restrict__ bc,
                 float* __restrict__ out) {
    extern __shared__ char smem[];
    const uint32_t smb = smem_u32(smem);
    uint32_t* wct16 = (uint32_t*)(smem + WCT_OFF);
    float*    kk    = (float*)(smem + KK_OFF);
    float*    bcs   = (float*)(smem + BC_OFF);
    uint32_t* vs16  = (uint32_t*)(smem + VS_OFF);

    const int t  = threadIdx.x;
    const int b  = blockIdx.z, bx = blockIdx.x, by = blockIdx.y;
    const int w  = t >> 5, lane = t & 31;

    // ---- static tiles: Wc -> wct16 (half2 channel pairs), kernels, bias ---
    for (int i = t; i < 2048; i += 256) {
        int j = i & 31, n = i >> 5;                 // j-major for coalescing
        wct16[j * WCT_STRIDE + n] =
            pack_h2(Wc[n * 64 + 2 * j], Wc[n * 64 + 2 * j + 1]);
    }
    for (int i = t; i < 576; i += 256) {
        int c = i / 9, j = i - c * 9;
        kk[c * 12 + j] = g_kern[b * 576 + i];
    }
    if (t < 64) bcs[t] = bc[t];

    // ---- halo loader: 16B cp.async, slab mapping (threads 0..159) ---------
    const int h0  = by * 8 - 1;
    const int w0p = bx * 32;
    const float* xb = x + (size_t)b * 64 * 16384;

    const int  lcl = t & 15;            // channel-in-chunk this thread loads
    const int  lk  = t >> 4;            // 16B chunk index 0..9 (t<160)
    const int  cb  = w0p - 4 + lk * 4;  // global col of chunk start
    const bool vc  = (unsigned)cb <= 124u;
    const bool lactive = t < 160;
    const float* lsrc0 = xb + (size_t)lcl * 16384 + (vc ? cb : 0);
    const uint32_t ldst0 = smb + XS_OFF + (uint32_t)(lcl * 1760 + lk * 16);

    auto load_chunk = [&](int c, int buf) {
        if (lactive) {
            const float* s0 = lsrc0 + (size_t)c * KC * 16384;
            uint32_t d0 = ldst0 + (uint32_t)buf * XS_BUF;
#pragma unroll
            for (int r = 0; r < 10; r++) {
                int gh = h0 + r;
                bool v = vc && ((unsigned)gh < 128u);
                cp_async16(d0 + r * 176, s0 + (v ? gh * 128 : 0), v ? 16u : 0u);
            }
        }
        CP_COMMIT();
    };

    load_chunk(0, 0);
    load_chunk(1, 1);

    // ---- GEMM thread mapping (R5-R9-verified addressing scheme) -----------
    const int wm = w >> 1, wn = w & 1;
    const int g = lane >> 2, tig = lane & 3;
    const int m_base = wm * 64;
    const int n_base = wn * 32;

    int rowoff[4];
#pragma unroll
    for (int mt = 0; mt < 4; mt++)
        rowoff[mt] = (wm * 2 + (mt >> 1)) * 36 + (mt & 1) * 16 + g;

    float acc[4][4][4];
#pragma unroll
    for (int mt = 0; mt < 4; mt++)
#pragma unroll
        for (int nt = 0; nt < 4; nt++)
#pragma unroll
            for (int r = 0; r < 4; r++) acc[mt][nt][r] = 0.f;

    // ---- phase-1 mapping: 16 px x 1 row x 1 ch per thread (as R9) ---------
    const int ch_l = t >> 4;            // channel in chunk 0..15
    const int prw  = (t >> 1) & 7;      // output row 0..7
    const int psh  = t & 1;             // col half 0..1
    const bool ch_even = (t & 16) == 0; // even-channel lanes store pairs

#pragma unroll
    for (int c = 0; c < 4; c++) {
        const int buf = c & 1;
        if (c < 3) { CP_WAIT(1); } else { CP_WAIT(0); }
        __syncthreads();

        // ---- phase 1: dwconv 3x3 + lrelu (R9 compute) + f16 pair pack -----
        {
            const float* xs = (const float*)(smem + XS_OFF + buf * XS_BUF);
            const float* kcp = kk + (c * KC + ch_l) * 12;
            const float* xbase = xs + ch_l * 440 + prw * 44 + 16 * psh;

            float a16[16];
#pragma unroll
            for (int p = 0; p < 16; p++) a16[p] = 0.f;

#pragma unroll
            for (int r = 0; r < 3; r++) {
                float k0 = kcp[r * 3 + 0];
                float k1 = kcp[r * 3 + 1];
                float k2 = kcp[r * 3 + 2];
                const float4* xr = (const float4*)(xbase + r * 44);
                float4 f0 = xr[0], f1 = xr[1], f2 = xr[2];
                float4 f3 = xr[3], f4 = xr[4], f5 = xr[5];
                float v[24] = {f0.x, f0.y, f0.z, f0.w, f1.x, f1.y, f1.z, f1.w,
                               f2.x, f2.y, f2.z, f2.w, f3.x, f3.y, f3.z, f3.w,
                               f4.x, f4.y, f4.z, f4.w, f5.x, f5.y, f5.z, f5.w};
#pragma unroll
                for (int p = 0; p < 16; p++)
                    a16[p] += v[p + 3] * k0 + v[p + 4] * k1 + v[p + 5] * k2;
            }

            // lrelu + f16 pack: po[q] = (px 2q, px 2q+1) of own channel
            uint32_t po[8];
#pragma unroll
            for (int q = 0; q < 8; q++) {
                float v0 = fmaxf(a16[2 * q],     0.1f * a16[2 * q]);
                float v1 = fmaxf(a16[2 * q + 1], 0.1f * a16[2 * q + 1]);
                po[q] = pack_h2(v0, v1);
            }
            // partner channel (t^16): same pixels, ch_l^1
            uint32_t outv[16];
#pragma unroll
            for (int q = 0; q < 8; q++) {
                uint32_t pr = __shfl_xor_sync(0xFFFFFFFFu, po[q], 16);
                // (even ch low, odd ch high) per pixel
                outv[2 * q]     = __byte_perm(po[q], pr, 0x5410);
                outv[2 * q + 1] = __byte_perm(po[q], pr, 0x7632);
            }
            if (ch_even) {
                uint32_t* vrow = vs16 + (ch_l >> 1) * KS16 + prw * 36 + 16 * psh;
#pragma unroll
                for (int q = 0; q < 4; q++)
                    *(uint4*)(vrow + 4 * q) = make_uint4(
                        outv[4 * q], outv[4 * q + 1],
                        outv[4 * q + 2], outv[4 * q + 3]);
            }
        }
        __syncthreads();

        // prefetch chunk c+2 into the buffer we just drained
        if (c < 2) load_chunk(c + 2, buf);

        // ---- phase 2: ONE m16n8k16 f16 k-step for this chunk --------------
        {
            uint32_t bf[4][2];
#pragma unroll
            for (int nt = 0; nt < 4; nt++) {
                int n = n_base + nt * 8 + g;
                bf[nt][0] = wct16[(c * 8 + tig) * WCT_STRIDE + n];
                bf[nt][1] = wct16[(c * 8 + 4 + tig) * WCT_STRIDE + n];
            }
            uint32_t af[4][4];
#pragma unroll
            for (int mt = 0; mt < 4; mt++) {
                af[mt][0] = vs16[tig * KS16 + rowoff[mt]];
                af[mt][1] = vs16[tig * KS16 + rowoff[mt] + 8];
                af[mt][2] = vs16[(4 + tig) * KS16 + rowoff[mt]];
                af[mt][3] = vs16[(4 + tig) * KS16 + rowoff[mt] + 8];
            }
#pragma unroll
            for (int mt = 0; mt < 4; mt++)
#pragma unroll
                for (int nt = 0; nt < 4; nt++)
                    mma_f16(acc[mt][nt], af[mt], bf[nt]);
        }
    }

    // ---- epilogue: unified stage (xs/vs region, dead) -> STG --------------
    float* stage = (float*)(smem + XS_OFF);
    float* obase = out + (size_t)b * 64 * 16384 + (size_t)(by * 8) * 128 + bx * 32;
    __syncthreads();
#pragma unroll
    for (int mt = 0; mt < 4; mt++)
#pragma unroll
        for (int nt = 0; nt < 4; nt++) {
            int ol = n_base + nt * 8 + 2 * tig;
            int p0 = m_base + mt * 16 + g;
            stage[ol * STG_STRIDE + p0]            = acc[mt][nt][0];
            stage[(ol + 1) * STG_STRIDE + p0]      = acc[mt][nt][1];
            stage[ol * STG_STRIDE + p0 + 8]        = acc[mt][nt][2];
            stage[(ol + 1) * STG_STRIDE + p0 + 8]  = acc[mt][nt][3];
        }
    __syncthreads();
#pragma unroll 8
    for (int j = 0; j < 64; j++) {
        int idx = t + 256 * j;
        int ol = idx >> 8, pix = idx & 255;
        float v = stage[ol * STG_STRIDE + pix] + bcs[ol];
        obase[(size_t)ol * 16384 + (pix >> 5) * 128 + (pix & 31)] = v;
    }
}

// ---------------------------------------------------------------------------
// Launch: inputs x, d, Wk1, Wk2, Wc, bc. Output float32 (16,64,128,128).
// ---------------------------------------------------------------------------
extern "C" void kernel_launch(void* const* d_in, const int* in_sizes, int n_in,
                              void* d_out, int out_size) {
    const float* x   = (const float*)d_in[0];
    const float* d   = (const float*)d_in[1];
    const float* Wk1 = (const float*)d_in[2];
    const float* Wk2 = (const float*)d_in[3];
    const float* Wc  = (const float*)d_in[4];
    const float* bc  = (const float*)d_in[5];
    float* out = (float*)d_out;

    gen_kern_kernel<<<dim3(16, 9), 256>>>(d, Wk1, Wk2);

    cudaFuncSetAttribute(da_conv_mma,
                         cudaFuncAttributeMaxDynamicSharedMemorySize,
                         SMEM_TOTAL);
    dim3 grid(4, 16, 16);
    da_conv_mma<<<grid, 256, SMEM_TOTAL>>>(x, Wc, bc, out);
}